// round 11
// baseline (speedup 1.0000x reference)
#include <cuda_runtime.h>
#include <math.h>

#define Bn 16
#define Cn 256
#define Hn 128
#define Wn 128
#define TH 8
#define TW 32
#define KC 4
#define PAD 4
#define NTHREADS 288
#define HR 16            // TH + 8 halo rows
#define HCP 44           // padded halo row stride (floats); data cols 0..39
#define TWP 36           // padded target row stride (floats); data cols 0..31
#define NS 10            // ceil(KC*HR*HCP / NTHREADS) = ceil(2816/288)
#define NT 4             // KC*TH*TWP / NTHREADS = 1152/288 exactly

__global__ __launch_bounds__(NTHREADS, 1)
void corr_norm_kernel(const float* __restrict__ src,
                      const float* __restrict__ tgt,
                      float* __restrict__ out)
{
    __shared__ __align__(16) float s_src[KC][HR][HCP];   // 11264 B
    __shared__ __align__(16) float s_tgt[KC][TH][TWP];   //  4608 B
    __shared__ __align__(16) float s_red[9][TH][TW];     //  9216 B

    const int tx  = threadIdx.x;           // 0..3 : 8-pixel groups along w
    const int ty  = threadIdx.y;           // 0..7 : h within tile
    const int tz  = threadIdx.z;           // 0..8 : dh (one displacement row)
    const int tid = tx + 4 * ty + 32 * tz;
    const int tx8 = tx * 8;

    const int b  = blockIdx.z;
    const int h0 = blockIdx.y * TH;
    const int wb = blockIdx.x * TW;

    float* s_srcF = &s_src[0][0][0];
    float* s_tgtF = &s_tgt[0][0][0];

    // ---- prefetch slot addressing (invariant across channel chunks) ----
    int  s_off[NS]; bool s_ok[NS]; bool s_in[NS];
#pragma unroll
    for (int i = 0; i < NS; i++) {
        int g   = tid + i * NTHREADS;                 // flat index into KC*HR*HCP
        s_in[i] = g < KC * HR * HCP;
        int gg  = s_in[i] ? g : 0;
        int cc  = gg / (HR * HCP);
        int rem = gg % (HR * HCP);
        int r   = rem / HCP;
        int col = rem % HCP;
        int gh = h0 - PAD + r;
        int gw = wb - PAD + col;
        s_ok[i]  = s_in[i] && (col < TW + 8)
                 && ((unsigned)gh < (unsigned)Hn) && ((unsigned)gw < (unsigned)Wn);
        s_off[i] = s_ok[i] ? (((b * Cn + cc) * Hn + gh) * Wn + gw) : 0;
    }
    int  t_off[NT]; bool t_ok[NT];
#pragma unroll
    for (int i = 0; i < NT; i++) {
        int g   = tid + i * NTHREADS;                 // flat index into KC*TH*TWP
        int cc  = g / (TH * TWP);
        int rem = g % (TH * TWP);
        int r   = rem / TWP;
        int col = rem % TWP;
        t_ok[i]  = col < TW;
        t_off[i] = t_ok[i] ? (((b * Cn + cc) * Hn + h0 + r) * Wn + wb + col) : 0;
    }

    // ---- prefetch chunk 0 into registers ----
    float pf_s[NS], pf_t[NT];
#pragma unroll
    for (int i = 0; i < NS; i++) pf_s[i] = s_ok[i] ? __ldg(src + s_off[i]) : 0.f;
#pragma unroll
    for (int i = 0; i < NT; i++) pf_t[i] = t_ok[i] ? __ldg(tgt + t_off[i]) : 0.f;

    // ---- accumulators: 9 dw x 8 pixels ----
    float acc[9][8];
#pragma unroll
    for (int dw = 0; dw < 9; dw++)
#pragma unroll
        for (int p = 0; p < 8; p++) acc[dw][p] = 0.f;

    // double-buffered per-channel operands (registers)
    float4 wb4[2][4];   // window: 16 floats, halo cols tx8 .. tx8+15
    float4 tb4[2][2];   // target:  8 floats, cols tx8 .. tx8+7

    // B is the register-buffer index (0/1); CC is the channel within the chunk.
#define LOADCH(B, CC) do {                                            \
        const float* wp_ = &s_src[CC][ty + tz][tx8];                  \
        wb4[B][0] = *(const float4*)(wp_);                            \
        wb4[B][1] = *(const float4*)(wp_ + 4);                        \
        wb4[B][2] = *(const float4*)(wp_ + 8);                        \
        wb4[B][3] = *(const float4*)(wp_ + 12);                       \
        const float* tp_ = &s_tgt[CC][ty][tx8];                       \
        tb4[B][0] = *(const float4*)(tp_);                            \
        tb4[B][1] = *(const float4*)(tp_ + 4);                        \
    } while (0)

#define FMACH(B) do {                                                 \
        const float* w_ = (const float*)&wb4[B][0];                   \
        const float* t_ = (const float*)&tb4[B][0];                   \
        _Pragma("unroll")                                             \
        for (int dw = 0; dw < 9; dw++)                                \
            _Pragma("unroll")                                         \
            for (int p = 0; p < 8; p++)                               \
                acc[dw][p] = fmaf(t_[p], w_[p + dw], acc[dw][p]);     \
    } while (0)

    for (int c0 = 0; c0 < Cn; c0 += KC) {
        // commit prefetched registers to shared
#pragma unroll
        for (int i = 0; i < NS; i++) if (s_in[i]) s_srcF[tid + i * NTHREADS] = pf_s[i];
#pragma unroll
        for (int i = 0; i < NT; i++) s_tgtF[tid + i * NTHREADS] = pf_t[i];
        __syncthreads();

        // software-pipelined: LDS of channel k+1 issued before FFMAs of channel k
        LOADCH(0, 0);        // ch0 -> buf0
        LOADCH(1, 1);        // ch1 -> buf1
        if (c0 + KC < Cn) {  // global prefetch for next chunk (overlaps compute)
            const float* sp = src + (size_t)(c0 + KC) * (Hn * Wn);
            const float* tp = tgt + (size_t)(c0 + KC) * (Hn * Wn);
#pragma unroll
            for (int i = 0; i < NS; i++) pf_s[i] = s_ok[i] ? __ldg(sp + s_off[i]) : 0.f;
#pragma unroll
            for (int i = 0; i < NT; i++) pf_t[i] = t_ok[i] ? __ldg(tp + t_off[i]) : 0.f;
        }
        FMACH(0);            // consume ch0
        LOADCH(0, 2);        // ch2 -> buf0
        FMACH(1);            // consume ch1
        LOADCH(1, 3);        // ch3 -> buf1
        FMACH(0);            // consume ch2  (bug was FMACH(2))
        FMACH(1);            // consume ch3  (bug was FMACH(3))
        __syncthreads();
    }

    // ---- fused relu + L2-normalize over 81 displacement channels ----
    float part[8];
#pragma unroll
    for (int p = 0; p < 8; p++) part[p] = 0.f;
#pragma unroll
    for (int dw = 0; dw < 9; dw++)
#pragma unroll
        for (int p = 0; p < 8; p++) {
            float v = fmaxf(acc[dw][p], 0.f);
            acc[dw][p] = v;
            part[p] = fmaf(v, v, part[p]);
        }
    *(float4*)&s_red[tz][ty][tx8]     = *(float4*)&part[0];
    *(float4*)&s_red[tz][ty][tx8 + 4] = *(float4*)&part[4];
    __syncthreads();

    float inv[8];
#pragma unroll
    for (int p = 0; p < 8; p++) inv[p] = 0.f;
#pragma unroll
    for (int z = 0; z < 9; z++) {
        float4 a = *(const float4*)&s_red[z][ty][tx8];
        float4 c = *(const float4*)&s_red[z][ty][tx8 + 4];
        inv[0] += a.x; inv[1] += a.y; inv[2] += a.z; inv[3] += a.w;
        inv[4] += c.x; inv[5] += c.y; inv[6] += c.z; inv[7] += c.w;
    }
#pragma unroll
    for (int p = 0; p < 8; p++) inv[p] = 1.f / fmaxf(sqrtf(inv[p]), 1e-12f);

    const int h = h0 + ty;
    const int w = wb + tx8;
#pragma unroll
    for (int dw = 0; dw < 9; dw++) {
        int d = tz * 9 + dw;
        float* op = &out[(((size_t)b * 81 + d) * Hn + h) * Wn + w];
        float4 o0, o1;
        o0.x = acc[dw][0] * inv[0];
        o0.y = acc[dw][1] * inv[1];
        o0.z = acc[dw][2] * inv[2];
        o0.w = acc[dw][3] * inv[3];
        o1.x = acc[dw][4] * inv[4];
        o1.y = acc[dw][5] * inv[5];
        o1.z = acc[dw][6] * inv[6];
        o1.w = acc[dw][7] * inv[7];
        *(float4*)(op)     = o0;
        *(float4*)(op + 4) = o1;
    }
}

extern "C" void kernel_launch(void* const* d_in, const int* in_sizes, int n_in,
                              void* d_out, int out_size)
{
    const float* src = (const float*)d_in[0];   // feature_source [16,256,128,128]
    const float* tgt = (const float*)d_in[1];   // feature_target [16,256,128,128]
    float* out = (float*)d_out;                 // [16,81,128,128]

    dim3 grid(Wn / TW, Hn / TH, Bn);            // (4, 16, 16) = 1024 blocks
    dim3 block(4, TH, 9);                       // 288 threads
    corr_norm_kernel<<<grid, block>>>(src, tgt, out);
}

// round 13
// speedup vs baseline: 1.9792x; 1.9792x over previous
#include <cuda_runtime.h>
#include <math.h>
#include <stdint.h>

#define Bn 16
#define Cn 256
#define Hn 128
#define Wn 128
#define TH 16
#define TW 32
#define KC 4
#define PAD 4
#define NTHREADS 384
#define HR 24                 // TH + 8
#define HC 40                 // TW + 8 (stride 40: conflict-free, verified)
#define S_F4 960              // KC*HR*HC/4 float4 slots per chunk
#define T_F4 512              // KC*TH*TW/4
#define NS4 3                 // ceil(960/384)
#define NT4 2                 // ceil(512/384)
#define SRC_BUF_B (KC*HR*HC*4)   // 15360 B per buffer
#define TGT_BUF_B (KC*TH*TW*4)   //  8192 B per buffer
#define HW (Hn*Wn)

__device__ __forceinline__ void cp16(uint32_t dst, const void* gsrc, int srcsize) {
    asm volatile("cp.async.cg.shared.global [%0], [%1], 16, %2;"
                 :: "r"(dst), "l"(gsrc), "r"(srcsize));
}
__device__ __forceinline__ void cp_commit() {
    asm volatile("cp.async.commit_group;" ::: "memory");
}
__device__ __forceinline__ void cp_wait0() {
    asm volatile("cp.async.wait_group 0;" ::: "memory");
}

__global__ __launch_bounds__(NTHREADS, 1)
void corr_norm_kernel(const float* __restrict__ src,
                      const float* __restrict__ tgt,
                      float* __restrict__ out)
{
    // ping-pong buffers: 2*(15360+8192) = 47104 B static smem
    __shared__ __align__(16) float s_src[2][KC][HR][HC];
    __shared__ __align__(16) float s_tgt[2][KC][TH][TW];

    const int tx  = threadIdx.x;           // 0..7  : 4-px groups along w
    const int ty  = threadIdx.y;           // 0..15 : h within tile
    const int tz  = threadIdx.z;           // 0..2  : dh group (3 rows each)
    const int tid = tx + 8 * ty + 128 * tz;

    const int b  = blockIdx.z;
    const int h0 = blockIdx.y * TH;
    const int wb = blockIdx.x * TW;

    const uint32_t s_base = (uint32_t)__cvta_generic_to_shared(&s_src[0][0][0][0]);
    const uint32_t t_base = (uint32_t)__cvta_generic_to_shared(&s_tgt[0][0][0][0]);

    // ---- float4 cp.async slot addressing (invariant across chunks) ----
    // src: flat float4 index over KC x HR x HC
    int  s_goff[NS4]; int s_sz[NS4]; bool s_in[NS4]; uint32_t s_dst[NS4];
#pragma unroll
    for (int i = 0; i < NS4; i++) {
        int g4  = tid + i * NTHREADS;
        s_in[i] = g4 < S_F4;
        int gg  = s_in[i] ? g4 : 0;
        int cc  = gg / (HR * HC / 4);          // 240 f4 per channel
        int rem = gg % (HR * HC / 4);
        int r   = rem / (HC / 4);              // 10 f4 per row
        int c4  = rem % (HC / 4);
        int gh  = h0 - PAD + r;
        int gw  = wb - PAD + 4 * c4;
        bool ok = s_in[i] && ((unsigned)gh < (unsigned)Hn) && (gw >= 0) && (gw <= Wn - 4);
        s_sz[i]   = ok ? 16 : 0;
        s_goff[i] = ok ? (((b * Cn + cc) * Hn + gh) * Wn + gw) : 0;
        s_dst[i]  = s_base + (uint32_t)g4 * 16u;
    }
    // tgt: flat float4 index over KC x TH x TW
    int  t_goff[NT4]; bool t_in[NT4]; uint32_t t_dst[NT4];
#pragma unroll
    for (int i = 0; i < NT4; i++) {
        int g4  = tid + i * NTHREADS;
        t_in[i] = g4 < T_F4;
        int gg  = t_in[i] ? g4 : 0;
        int cc  = gg / (TH * TW / 4);          // 128 f4 per channel
        int rem = gg % (TH * TW / 4);
        int r   = rem / (TW / 4);
        int c4  = rem % (TW / 4);
        t_goff[i] = ((b * Cn + cc) * Hn + h0 + r) * Wn + wb + 4 * c4;
        t_dst[i]  = t_base + (uint32_t)g4 * 16u;
    }

#define ISSUE_CHUNK(C0, P) do {                                               \
        const float* sp_ = src + (size_t)(C0) * HW;                           \
        const float* tp_ = tgt + (size_t)(C0) * HW;                           \
        _Pragma("unroll")                                                     \
        for (int i = 0; i < NS4; i++)                                         \
            if (s_in[i]) cp16(s_dst[i] + (P) * SRC_BUF_B, sp_ + s_goff[i], s_sz[i]); \
        _Pragma("unroll")                                                     \
        for (int i = 0; i < NT4; i++)                                         \
            if (t_in[i]) cp16(t_dst[i] + (P) * TGT_BUF_B, tp_ + t_goff[i], 16);      \
        cp_commit();                                                          \
    } while (0)

    // ---- accumulators: 3 dh rows x 9 dw x 4 pixels = 108 fp32 ----
    float acc[3][9][4];
#pragma unroll
    for (int r = 0; r < 3; r++)
#pragma unroll
        for (int dw = 0; dw < 9; dw++)
#pragma unroll
            for (int p = 0; p < 4; p++) acc[r][dw][p] = 0.f;

    // prologue: fill buffer 0 with chunk 0
    ISSUE_CHUNK(0, 0);
    cp_wait0();
    __syncthreads();

    int p = 0;
    for (int c0 = 0; c0 < Cn; c0 += KC) {
        // async-fetch next chunk into the other buffer (overlaps compute)
        if (c0 + KC < Cn) ISSUE_CHUNK(c0 + KC, p ^ 1);
        else              cp_commit();   // keep group count consistent

        // compute chunk c0 from buffer p (proven R1 core)
#pragma unroll
        for (int cc = 0; cc < KC; cc++) {
            float tt[4];
            *(float4*)tt = *(const float4*)&s_tgt[p][cc][ty][tx * 4];
#pragma unroll
            for (int r = 0; r < 3; r++) {
                const float* wp = &s_src[p][cc][ty + tz * 3 + r][tx * 4];
                float win[12];
                *(float4*)&win[0] = *(const float4*)(wp);
                *(float4*)&win[4] = *(const float4*)(wp + 4);
                *(float4*)&win[8] = *(const float4*)(wp + 8);
#pragma unroll
                for (int dw = 0; dw < 9; dw++)
#pragma unroll
                    for (int q = 0; q < 4; q++)
                        acc[r][dw][q] = fmaf(tt[q], win[dw + q], acc[r][dw][q]);
            }
        }

        cp_wait0();          // next chunk landed
        __syncthreads();     // one barrier per iteration
        p ^= 1;
    }

    // ---- fused relu + L2-normalize over the 81 displacement channels ----
    // s_red aliases the (now dead) smem buffers
    float (*s_red)[TH][TW] = reinterpret_cast<float (*)[TH][TW]>(&s_src[0][0][0][0]);

    float part[4] = {0.f, 0.f, 0.f, 0.f};
#pragma unroll
    for (int r = 0; r < 3; r++)
#pragma unroll
        for (int dw = 0; dw < 9; dw++)
#pragma unroll
            for (int q = 0; q < 4; q++) {
                float v = fmaxf(acc[r][dw][q], 0.f);
                acc[r][dw][q] = v;
                part[q] = fmaf(v, v, part[q]);
            }
    *(float4*)&s_red[tz][ty][tx * 4] = *(float4*)part;
    __syncthreads();

    float inv[4];
#pragma unroll
    for (int q = 0; q < 4; q++) {
        float s = s_red[0][ty][tx * 4 + q]
                + s_red[1][ty][tx * 4 + q]
                + s_red[2][ty][tx * 4 + q];
        inv[q] = 1.f / fmaxf(sqrtf(s), 1e-12f);
    }

    const int h = h0 + ty;
    const int w = wb + tx * 4;
#pragma unroll
    for (int r = 0; r < 3; r++) {
        int dh = tz * 3 + r;
#pragma unroll
        for (int dw = 0; dw < 9; dw++) {
            int d = dh * 9 + dw;
            float4 o;
            o.x = acc[r][dw][0] * inv[0];
            o.y = acc[r][dw][1] * inv[1];
            o.z = acc[r][dw][2] * inv[2];
            o.w = acc[r][dw][3] * inv[3];
            *(float4*)&out[(((size_t)b * 81 + d) * Hn + h) * Wn + w] = o;
        }
    }
}

extern "C" void kernel_launch(void* const* d_in, const int* in_sizes, int n_in,
                              void* d_out, int out_size)
{
    const float* src = (const float*)d_in[0];   // feature_source [16,256,128,128]
    const float* tgt = (const float*)d_in[1];   // feature_target [16,256,128,128]
    float* out = (float*)d_out;                 // [16,81,128,128]

    dim3 grid(Wn / TW, Hn / TH, Bn);            // (4, 8, 16) = 512 blocks
    dim3 block(8, TH, 3);                       // 384 threads
    corr_norm_kernel<<<grid, block>>>(src, tgt, out);
}

// round 14
// speedup vs baseline: 2.0699x; 1.0458x over previous
#include <cuda_runtime.h>
#include <math.h>
#include <stdint.h>

#define Bn 16
#define Cn 256
#define Hn 128
#define Wn 128
#define TH 16
#define TW 16
#define KC 4
#define PAD 4
#define NTHREADS 192
#define HR 24                 // TH + 8 halo rows
#define HCU 24                // used halo cols (TW + 8)
#define HCS 48                // smem row stride (floats): ≡16 mod 32 words -> conflict-free, 16B-aligned rows
#define S_F4 576              // KC*HR*(HCU/4) f4 slots per chunk = 4*24*6
#define T_F4 256              // KC*TH*(TW/4)  = 4*16*4
#define NS4 3                 // 576/192 exact
#define NT4 2                 // ceil(256/192)
#define SRC_BUF_B (KC*HR*HCS*4)   // 18432 B per buffer
#define TGT_BUF_B (KC*TH*TW*4)    //  4096 B per buffer
#define HW (Hn*Wn)

__device__ __forceinline__ void cp16(uint32_t dst, const void* gsrc, int srcsize) {
    asm volatile("cp.async.cg.shared.global [%0], [%1], 16, %2;"
                 :: "r"(dst), "l"(gsrc), "r"(srcsize));
}
__device__ __forceinline__ void cp_commit() {
    asm volatile("cp.async.commit_group;" ::: "memory");
}
__device__ __forceinline__ void cp_wait0() {
    asm volatile("cp.async.wait_group 0;" ::: "memory");
}

__global__ __launch_bounds__(NTHREADS, 2)
void corr_norm_kernel(const float* __restrict__ src,
                      const float* __restrict__ tgt,
                      float* __restrict__ out)
{
    // ping-pong buffers: 2*(18432+4096) = 45056 B static smem (2 blocks/SM = 90KB < 228KB)
    __shared__ __align__(16) float s_src[2][KC][HR][HCS];
    __shared__ __align__(16) float s_tgt[2][KC][TH][TW];

    const int tx  = threadIdx.x;           // 0..3  : 4-px groups along w
    const int ty  = threadIdx.y;           // 0..15 : h within tile
    const int tz  = threadIdx.z;           // 0..2  : dh group (3 rows each)
    const int tid = tx + 4 * ty + 64 * tz;

    const int b  = blockIdx.z;
    const int h0 = blockIdx.y * TH;
    const int wb = blockIdx.x * TW;

    const uint32_t s_base = (uint32_t)__cvta_generic_to_shared(&s_src[0][0][0][0]);
    const uint32_t t_base = (uint32_t)__cvta_generic_to_shared(&s_tgt[0][0][0][0]);

    // ---- f4 cp.async slot addressing (invariant across chunks) ----
    // src: flat f4 index over KC x HR x (HCU/4=6); smem rows padded to HCS
    int s_goff[NS4]; int s_sz[NS4]; uint32_t s_dst[NS4];
#pragma unroll
    for (int i = 0; i < NS4; i++) {
        int g4  = tid + i * NTHREADS;          // 0..575, exact fit
        int cc  = g4 / (HR * 6);
        int rem = g4 % (HR * 6);
        int r   = rem / 6;
        int c4  = rem % 6;
        int gh  = h0 - PAD + r;
        int gw  = wb - PAD + 4 * c4;
        bool ok = ((unsigned)gh < (unsigned)Hn) && (gw >= 0) && (gw <= Wn - 4);
        s_sz[i]   = ok ? 16 : 0;
        s_goff[i] = ok ? (((b * Cn + cc) * Hn + gh) * Wn + gw) : 0;
        s_dst[i]  = s_base + (uint32_t)(((cc * HR + r) * HCS + 4 * c4) * 4);
    }
    // tgt: flat f4 index over KC x TH x (TW/4=4)
    int t_goff[NT4]; bool t_in[NT4]; uint32_t t_dst[NT4];
#pragma unroll
    for (int i = 0; i < NT4; i++) {
        int g4  = tid + i * NTHREADS;
        t_in[i] = g4 < T_F4;
        int gg  = t_in[i] ? g4 : 0;
        int cc  = gg / (TH * 4);
        int rem = gg % (TH * 4);
        int r   = rem / 4;
        int c4  = rem % 4;
        t_goff[i] = ((b * Cn + cc) * Hn + h0 + r) * Wn + wb + 4 * c4;
        t_dst[i]  = t_base + (uint32_t)gg * 16u;
    }

#define ISSUE_CHUNK(C0, P) do {                                               \
        const float* sp_ = src + (size_t)(C0) * HW;                           \
        const float* tp_ = tgt + (size_t)(C0) * HW;                           \
        _Pragma("unroll")                                                     \
        for (int i = 0; i < NS4; i++)                                         \
            cp16(s_dst[i] + (P) * SRC_BUF_B, sp_ + s_goff[i], s_sz[i]);       \
        _Pragma("unroll")                                                     \
        for (int i = 0; i < NT4; i++)                                         \
            if (t_in[i]) cp16(t_dst[i] + (P) * TGT_BUF_B, tp_ + t_goff[i], 16); \
        cp_commit();                                                          \
    } while (0)

    // ---- accumulators: 3 dh rows x 9 dw x 4 pixels = 108 fp32 ----
    float acc[3][9][4];
#pragma unroll
    for (int r = 0; r < 3; r++)
#pragma unroll
        for (int dw = 0; dw < 9; dw++)
#pragma unroll
            for (int p = 0; p < 4; p++) acc[r][dw][p] = 0.f;

    // prologue: fill buffer 0 with chunk 0
    ISSUE_CHUNK(0, 0);
    cp_wait0();
    __syncthreads();

    int p = 0;
    for (int c0 = 0; c0 < Cn; c0 += KC) {
        // async-fetch next chunk into the other buffer (overlaps compute)
        if (c0 + KC < Cn) ISSUE_CHUNK(c0 + KC, p ^ 1);
        else              cp_commit();   // keep group count consistent

        // compute chunk c0 from buffer p (proven core, same per-thread geometry)
#pragma unroll
        for (int cc = 0; cc < KC; cc++) {
            float tt[4];
            *(float4*)tt = *(const float4*)&s_tgt[p][cc][ty][tx * 4];
#pragma unroll
            for (int r = 0; r < 3; r++) {
                const float* wp = &s_src[p][cc][ty + tz * 3 + r][tx * 4];
                float win[12];
                *(float4*)&win[0] = *(const float4*)(wp);
                *(float4*)&win[4] = *(const float4*)(wp + 4);
                *(float4*)&win[8] = *(const float4*)(wp + 8);
#pragma unroll
                for (int dw = 0; dw < 9; dw++)
#pragma unroll
                    for (int q = 0; q < 4; q++)
                        acc[r][dw][q] = fmaf(tt[q], win[dw + q], acc[r][dw][q]);
            }
        }

        cp_wait0();          // next chunk landed
        __syncthreads();     // one barrier per iteration
        p ^= 1;
    }

    // ---- fused relu + L2-normalize over the 81 displacement channels ----
    // s_red aliases the (now dead) smem buffers
    float (*s_red)[TH][TW] = reinterpret_cast<float (*)[TH][TW]>(&s_src[0][0][0][0]);

    float part[4] = {0.f, 0.f, 0.f, 0.f};
#pragma unroll
    for (int r = 0; r < 3; r++)
#pragma unroll
        for (int dw = 0; dw < 9; dw++)
#pragma unroll
            for (int q = 0; q < 4; q++) {
                float v = fmaxf(acc[r][dw][q], 0.f);
                acc[r][dw][q] = v;
                part[q] = fmaf(v, v, part[q]);
            }
    *(float4*)&s_red[tz][ty][tx * 4] = *(float4*)part;
    __syncthreads();

    float inv[4];
#pragma unroll
    for (int q = 0; q < 4; q++) {
        float s = s_red[0][ty][tx * 4 + q]
                + s_red[1][ty][tx * 4 + q]
                + s_red[2][ty][tx * 4 + q];
        inv[q] = 1.f / fmaxf(sqrtf(s), 1e-12f);
    }

    const int h = h0 + ty;
    const int w = wb + tx * 4;
#pragma unroll
    for (int r = 0; r < 3; r++) {
        int dh = tz * 3 + r;
#pragma unroll
        for (int dw = 0; dw < 9; dw++) {
            int d = dh * 9 + dw;
            float4 o;
            o.x = acc[r][dw][0] * inv[0];
            o.y = acc[r][dw][1] * inv[1];
            o.z = acc[r][dw][2] * inv[2];
            o.w = acc[r][dw][3] * inv[3];
            *(float4*)&out[(((size_t)b * 81 + d) * Hn + h) * Wn + w] = o;
        }
    }
}

extern "C" void kernel_launch(void* const* d_in, const int* in_sizes, int n_in,
                              void* d_out, int out_size)
{
    const float* src = (const float*)d_in[0];   // feature_source [16,256,128,128]
    const float* tgt = (const float*)d_in[1];   // feature_target [16,256,128,128]
    float* out = (float*)d_out;                 // [16,81,128,128]

    dim3 grid(Wn / TW, Hn / TH, Bn);            // (8, 8, 16) = 1024 blocks
    dim3 block(4, TH, 3);                       // 192 threads, 2 blocks/SM
    corr_norm_kernel<<<grid, block>>>(src, tgt, out);
}